// round 13
// baseline (speedup 1.0000x reference)
#include <cuda_runtime.h>
#include <math.h>

#define Bsz    2048
#define Hd     256
#define INd    64
#define KTERMS 8
#define ROWS   14          // rows per CTA (7 f32x2 pairs)
#define NCTAS  148
#define NTHR   512
#define PITCH  20          // floats per smem act row (80B, odd 16B-granule stride)
#define SLOT   18          // u64 per export slot (144B, odd 16B-granule stride)

typedef unsigned long long ull;

// Pre-transposed weights (L2-resident)
__device__ float g_whT[Hd*Hd];     // whT[j*Hd+k]   = wh[k*Hd+j]
__device__ float g_woutT[Hd*Hd];   // woutT[j*Hd+k] = wout[k*Hd+j]
__device__ float g_wxT[INd*Hd];    // wxT[i*Hd+k]   = wx[k*INd+i]

// ---------------- packed f32x2 helpers ----------------
__device__ __forceinline__ ull pack2(float lo, float hi) {
    ull r; asm("mov.b64 %0, {%1,%2};" : "=l"(r) : "f"(lo), "f"(hi)); return r;
}
__device__ __forceinline__ void unpack2(ull v, float& lo, float& hi) {
    asm("mov.b64 {%0,%1}, %2;" : "=f"(lo), "=f"(hi) : "l"(v));
}
__device__ __forceinline__ ull fma2(ull a, ull b, ull c) {
    ull d; asm("fma.rn.f32x2 %0, %1, %2, %3;" : "=l"(d) : "l"(a), "l"(b), "l"(c)); return d;
}
__device__ __forceinline__ ull mul2(ull a, ull b) {
    ull d; asm("mul.rn.f32x2 %0, %1, %2;" : "=l"(d) : "l"(a), "l"(b)); return d;
}
__device__ __forceinline__ ull add2(ull a, ull b) {
    ull d; asm("add.rn.f32x2 %0, %1, %2;" : "=l"(d) : "l"(a), "l"(b)); return d;
}

// load 7 u64 (14 floats) from an act row
__device__ __forceinline__ void ldrow7(const float* p, ull v[7]) {
    const ulonglong2* q = reinterpret_cast<const ulonglong2*>(p);
    ulonglong2 a = q[0], b = q[1], c = q[2];
    v[0]=a.x; v[1]=a.y; v[2]=b.x; v[3]=b.y; v[4]=c.x; v[5]=c.y;
    v[6] = reinterpret_cast<const ull*>(p)[6];
}

// C=2 partial GEMM for j-group g: j = 4m+g, phys(j) = m + NJ*g.
// acc0/acc1: accumulators for columns ct2 and ct2+1, 7 row-pairs each.
template<int NJ>
__device__ __forceinline__ void gemmC2(const float* __restrict__ Wt, int ct2, int g,
                                       const float* sIn, ull acc0[7], ull acc1[7]) {
    const float* wp = Wt + g * Hd + ct2;
    const float* sp = sIn + (NJ * g) * PITCH;
#pragma unroll 8
    for (int m = 0; m < NJ; ++m) {
        float2 w2 = *reinterpret_cast<const float2*>(wp);
        ull v[7];
        ldrow7(sp, v);
        ull w0 = pack2(w2.x, w2.x), w1 = pack2(w2.y, w2.y);
#pragma unroll
        for (int t = 0; t < 7; ++t) {
            acc0[t] = fma2(w0, v[t], acc0[t]);
            acc1[t] = fma2(w1, v[t], acc1[t]);
        }
        wp += 4 * Hd;
        sp += PITCH;
    }
}

// export 14 u64: col0 pairs at u64 0..6, col1 pairs at u64 8..14
__device__ __forceinline__ void exportP(ull* p, const ull a0[7], const ull a1[7]) {
    ulonglong2* q = reinterpret_cast<ulonglong2*>(p);
    q[0] = make_ulonglong2(a0[0], a0[1]);
    q[1] = make_ulonglong2(a0[2], a0[3]);
    q[2] = make_ulonglong2(a0[4], a0[5]);
    p[6] = a0[6];
    q[4] = make_ulonglong2(a1[0], a1[1]);
    q[5] = make_ulonglong2(a1[2], a1[3]);
    q[6] = make_ulonglong2(a1[4], a1[5]);
    p[14] = a1[6];
}

// merge across 4 groups. HALF=0: pairs 0..3 (m[0..3]); HALF=1: pairs 4..6 (m[0..2]).
template<int HALF>
__device__ __forceinline__ void mergeP(const ull* sRed, int sidx, int coff, ull m[4]) {
    m[0] = m[1] = m[2] = m[3] = 0ull;
#pragma unroll
    for (int gp = 0; gp < 4; ++gp) {
        const ull* p = sRed + (gp * 128 + sidx) * SLOT + coff;
        if (HALF == 0) {
            ulonglong2 a = reinterpret_cast<const ulonglong2*>(p)[0];
            ulonglong2 b = reinterpret_cast<const ulonglong2*>(p)[1];
            m[0] = add2(m[0], a.x); m[1] = add2(m[1], a.y);
            m[2] = add2(m[2], b.x); m[3] = add2(m[3], b.y);
        } else {
            ulonglong2 a = reinterpret_cast<const ulonglong2*>(p)[0];
            m[0] = add2(m[0], a.x); m[1] = add2(m[1], a.y);
            m[2] = add2(m[2], p[2]);
        }
    }
}

// store merged slice to act row (HALF=0: u64 0..3, HALF=1: u64 4..6)
template<int HALF>
__device__ __forceinline__ void st_slice(float* rowbase, const ull m[4]) {
    ull* p = reinterpret_cast<ull*>(rowbase) + HALF * 4;
    reinterpret_cast<ulonglong2*>(p)[0] = make_ulonglong2(m[0], m[1]);
    if (HALF == 0) reinterpret_cast<ulonglong2*>(p)[1] = make_ulonglong2(m[2], m[3]);
    else           p[2] = m[2];
}

// ---------------- merged transpose ----------------
__global__ void transpose_all(const float* __restrict__ wh,
                              const float* __restrict__ wout,
                              const float* __restrict__ wx) {
    __shared__ float tile[32][33];
    int b = blockIdx.x;
    const float* in; float* out; int rows, cols, bx;
    if (b < 64)       { in = wh;   out = g_whT;   rows = Hd; cols = Hd;  bx = b; }
    else if (b < 128) { in = wout; out = g_woutT; rows = Hd; cols = Hd;  bx = b - 64; }
    else              { in = wx;   out = g_wxT;   rows = Hd; cols = INd; bx = b - 128; }
    int nbx = cols / 32;
    int c0 = (bx % nbx) * 32, r0 = (bx / nbx) * 32;
    for (int dy = threadIdx.y; dy < 32; dy += 8)
        tile[dy][threadIdx.x] = in[(r0 + dy) * cols + (c0 + threadIdx.x)];
    __syncthreads();
    for (int dy = threadIdx.y; dy < 32; dy += 8)
        out[(c0 + dy) * rows + (r0 + threadIdx.x)] = tile[threadIdx.x][dy];
}

// ---------------- pipeline body (templated on merge half) ----------------
template<int HALF>
__device__ __forceinline__ void run_pipeline(
    int tid, int g, int ct2, int mycol, int row0,
    ull* sRed, float* sA, float* sB, float* sXx, float* sXd,
    const float* __restrict__ b0, const float* __restrict__ b1,
    float* __restrict__ out) {

    const int NP = (HALF == 0) ? 4 : 3;
    const int myrow = (mycol >> 2) + ((mycol & 3) << 6);   // phys(mycol)
    const int sidx  = mycol >> 1;
    const int coff  = (mycol & 1) * 8 + HALF * 4;
    ull* myslot = sRed + (g * 128 + (ct2 >> 1)) * SLOT;

    float bk0 = b0[mycol];
    float bk1 = b1[mycol];

    ull gate[4], dth[4], hd[4];
    ull a0[7], a1[7];

    // ---- P1: l1 = x@wxT + h@whT + b0 -> gate, relu -> sB
#pragma unroll
    for (int t = 0; t < 7; ++t) { a0[t] = 0ull; a1[t] = 0ull; }
    gemmC2<16>(g_wxT, ct2, g, sXx, a0, a1);
    gemmC2<64>(g_whT, ct2, g, sA, a0, a1);
    exportP(myslot, a0, a1);
    __syncthreads();
    {
        ull m[4];
        mergeP<HALF>(sRed, sidx, coff, m);
        ull bp = pack2(bk0, bk0);
        ull relu[4];
#pragma unroll
        for (int t = 0; t < NP; ++t) {
            m[t] = add2(m[t], bp);
            float a, b; unpack2(m[t], a, b);
            float ga = (a > 0.f) ? 1.f : 0.f;
            float gb = (b > 0.f) ? 1.f : 0.f;
            gate[t] = pack2(ga, gb);
            relu[t] = pack2(ga * a, gb * b);
        }
        st_slice<HALF>(sB + myrow * PITCH, relu);
    }
    __syncthreads();

    // ---- P2: uu = xdot@wxT ; gated-u -> sA
#pragma unroll
    for (int t = 0; t < 7; ++t) { a0[t] = 0ull; a1[t] = 0ull; }
    gemmC2<16>(g_wxT, ct2, g, sXd, a0, a1);
    exportP(myslot, a0, a1);
    __syncthreads();
    {
        ull m[4];
        mergeP<HALF>(sRed, sidx, coff, m);
#pragma unroll
        for (int t = 0; t < NP; ++t) m[t] = mul2(m[t], gate[t]);
        st_slice<HALF>(sA + myrow * PITCH, m);
    }
    __syncthreads();

    // ---- P3: lout = relu@woutT + b1 -> dth
#pragma unroll
    for (int t = 0; t < 7; ++t) { a0[t] = 0ull; a1[t] = 0ull; }
    gemmC2<64>(g_woutT, ct2, g, sB, a0, a1);
    exportP(myslot, a0, a1);
    __syncthreads();
    {
        ull m[4];
        mergeP<HALF>(sRed, sidx, coff, m);
        ull bp = pack2(bk1, bk1);
#pragma unroll
        for (int t = 0; t < NP; ++t) {
            ull L = add2(m[t], bp);
            float a, b; unpack2(L, a, b);
            float ta = tanhf(a), tb = tanhf(b);
            dth[t] = pack2(1.f - ta * ta, 1.f - tb * tb);
        }
    }
    __syncthreads();

    // ---- P4: jx = gated-u@woutT ; curr = dth*jx -> sA ; hdot = curr
#pragma unroll
    for (int t = 0; t < 7; ++t) { a0[t] = 0ull; a1[t] = 0ull; }
    gemmC2<64>(g_woutT, ct2, g, sA, a0, a1);
    exportP(myslot, a0, a1);
    __syncthreads();
    {
        ull m[4];
        mergeP<HALF>(sRed, sidx, coff, m);
#pragma unroll
        for (int t = 0; t < NP; ++t) m[t] = mul2(m[t], dth[t]);
        st_slice<HALF>(sA + myrow * PITCH, m);
#pragma unroll
        for (int t = 0; t < NP; ++t) hd[t] = m[t];
    }
    __syncthreads();

    // ---- 8 Jh-power iterations
    for (int it = 0; it < KTERMS; ++it) {
#pragma unroll
        for (int t = 0; t < 7; ++t) { a0[t] = 0ull; a1[t] = 0ull; }
        gemmC2<64>(g_whT, ct2, g, sA, a0, a1);
        exportP(myslot, a0, a1);
        __syncthreads();
        {
            ull m[4];
            mergeP<HALF>(sRed, sidx, coff, m);
#pragma unroll
            for (int t = 0; t < NP; ++t) m[t] = mul2(m[t], gate[t]);
            st_slice<HALF>(sB + myrow * PITCH, m);
        }
        __syncthreads();
#pragma unroll
        for (int t = 0; t < 7; ++t) { a0[t] = 0ull; a1[t] = 0ull; }
        gemmC2<64>(g_woutT, ct2, g, sB, a0, a1);
        exportP(myslot, a0, a1);
        __syncthreads();
        {
            ull m[4];
            mergeP<HALF>(sRed, sidx, coff, m);
#pragma unroll
            for (int t = 0; t < NP; ++t) m[t] = mul2(m[t], dth[t]);
            st_slice<HALF>(sA + myrow * PITCH, m);
#pragma unroll
            for (int t = 0; t < NP; ++t) hd[t] = add2(hd[t], m[t]);
        }
        __syncthreads();
    }

    // ---- write h_dot: (mycol, rows row0 + HALF*8 + 2p)
#pragma unroll
    for (int t = 0; t < NP; ++t) {
        float a, b; unpack2(hd[t], a, b);
        int ro = row0 + HALF * 8 + 2 * t;
        if (ro < Bsz)     out[ro       * Hd + mycol] = a;
        if (ro + 1 < Bsz) out[(ro + 1) * Hd + mycol] = b;
    }
}

// ---------------- fused kernel: 1 CTA/SM, 512 threads, 14 rows ----------------
__global__ void __launch_bounds__(NTHR, 1)
fused_kernel(const float* __restrict__ hin, const float* __restrict__ xin,
             const float* __restrict__ xdin, const float* __restrict__ b0,
             const float* __restrict__ b1, float* __restrict__ out) {
    extern __shared__ __align__(16) char smraw[];
    ull*   sRed = reinterpret_cast<ull*>(smraw);                 // [512][SLOT]
    float* sA   = reinterpret_cast<float*>(sRed + NTHR * SLOT);  // [256][PITCH]
    float* sB   = sA + Hd * PITCH;                               // [256][PITCH]
    float* sXx  = sB + Hd * PITCH;                               // [64][PITCH]
    float* sXd  = sXx + INd * PITCH;                             // [64][PITCH]

    const int bid = blockIdx.x;
    const int row0 = bid * ROWS;
    if (row0 >= Bsz) return;                                     // bid 147 idle

    const int tid  = threadIdx.x;
    const int warp = tid >> 5;
    const int lane = tid & 31;
    const int g    = warp >> 2;                 // j-group 0..3 (warp-uniform, 4 warps each)
    const int ct   = ((warp & 3) << 5) + lane;  // col-thread 0..127; owns cols 2ct, 2ct+1
    const int ct2  = ct << 1;

    // merge/pointwise ownership: thread -> (mycol, half)
    const int mycol = ((tid & 127) << 1) + ((tid >> 7) & 1);
    const int half  = tid >> 8;                 // 0: pairs 0-3, 1: pairs 4-6

    // ---- stage inputs (transposed + phys-permuted); clamp tail rows
    for (int e = tid; e < ROWS * Hd; e += NTHR) {
        int r = e >> 8, j = e & 255;
        int rr = row0 + r; if (rr > Bsz - 1) rr = Bsz - 1;
        int pr = (j >> 2) + ((j & 3) << 6);
        sA[pr * PITCH + r] = hin[rr * Hd + j];
    }
    for (int e = tid; e < ROWS * INd; e += NTHR) {
        int r = e >> 6, i = e & 63;
        int rr = row0 + r; if (rr > Bsz - 1) rr = Bsz - 1;
        int pr = (i >> 2) + ((i & 3) << 4);
        sXx[pr * PITCH + r] = xin[rr * INd + i];
        sXd[pr * PITCH + r] = xdin[rr * INd + i];
    }
    __syncthreads();

    if (half == 0)
        run_pipeline<0>(tid, g, ct2, mycol, row0, sRed, sA, sB, sXx, sXd, b0, b1, out);
    else
        run_pipeline<1>(tid, g, ct2, mycol, row0, sRed, sA, sB, sXx, sXd, b0, b1, out);
}

#define SMEM_BYTES (NTHR * SLOT * 8 + (2 * Hd + 2 * INd) * PITCH * 4)

extern "C" void kernel_launch(void* const* d_in, const int* in_sizes, int n_in,
                              void* d_out, int out_size) {
    (void)in_sizes; (void)n_in; (void)out_size;
    const float* h_   = (const float*)d_in[0];
    const float* x    = (const float*)d_in[1];
    const float* xdot = (const float*)d_in[2];
    const float* wx   = (const float*)d_in[3];
    const float* wh   = (const float*)d_in[4];
    const float* wout = (const float*)d_in[5];
    const float* b0   = (const float*)d_in[6];
    const float* b1   = (const float*)d_in[7];
    float* out = (float*)d_out;

    cudaFuncSetAttribute(fused_kernel, cudaFuncAttributeMaxDynamicSharedMemorySize, SMEM_BYTES);
    transpose_all<<<144, dim3(32, 8)>>>(wh, wout, wx);
    fused_kernel<<<NCTAS, NTHR, SMEM_BYTES>>>(h_, x, xdot, b0, b1, out);
}

// round 14
// speedup vs baseline: 1.1624x; 1.1624x over previous
#include <cuda_runtime.h>
#include <math.h>

#define Bsz    2048
#define Hd     256
#define INd    64
#define KTERMS 8
#define ROWS   14          // rows per CTA: A-block 8 + B-block 6
#define NCTAS  148
#define NTHR   256
#define PITCH  12          // floats per smem act row (48B, odd 16B-granule stride)
#define SLOT   18          // u64 per export slot (144B, odd 16B-granule stride)

typedef unsigned long long ull;

// Pre-transposed weights (L2-resident)
__device__ float g_whT[Hd*Hd];     // whT[j*Hd+k]   = wh[k*Hd+j]
__device__ float g_woutT[Hd*Hd];   // woutT[j*Hd+k] = wout[k*Hd+j]
__device__ float g_wxT[INd*Hd];    // wxT[i*Hd+k]   = wx[k*INd+i]

// ---------------- packed f32x2 helpers ----------------
__device__ __forceinline__ ull pack2(float lo, float hi) {
    ull r; asm("mov.b64 %0, {%1,%2};" : "=l"(r) : "f"(lo), "f"(hi)); return r;
}
__device__ __forceinline__ void unpack2(ull v, float& lo, float& hi) {
    asm("mov.b64 {%0,%1}, %2;" : "=f"(lo), "=f"(hi) : "l"(v));
}
__device__ __forceinline__ ull fma2(ull a, ull b, ull c) {
    ull d; asm("fma.rn.f32x2 %0, %1, %2, %3;" : "=l"(d) : "l"(a), "l"(b), "l"(c)); return d;
}
__device__ __forceinline__ ull mul2(ull a, ull b) {
    ull d; asm("mul.rn.f32x2 %0, %1, %2;" : "=l"(d) : "l"(a), "l"(b)); return d;
}
__device__ __forceinline__ ull add2(ull a, ull b) {
    ull d; asm("add.rn.f32x2 %0, %1, %2;" : "=l"(d) : "l"(a), "l"(b)); return d;
}

// load PAIRS u64 from an act row
template<int PAIRS>
__device__ __forceinline__ void ldrowP(const float* p, ull v[PAIRS]) {
    ulonglong2 a = *reinterpret_cast<const ulonglong2*>(p);
    v[0] = a.x; v[1] = a.y;
    if (PAIRS == 3) {
        v[2] = reinterpret_cast<const ull*>(p)[2];
    } else if (PAIRS == 4) {
        ulonglong2 b = reinterpret_cast<const ulonglong2*>(p)[1];
        v[2] = b.x; v[3] = b.y;
    }
}

// Dual-block C=4 partial GEMM for j-group g: ONE weight load feeds A(4 pairs) + B(3 pairs).
// j = 4*NJ4*g + jm + 4*jd ; phys(j) = NJ4*g + jm*Q + jd
template<int NJ4, int Q>
__device__ __forceinline__ void gemm_dual(const float* __restrict__ Wt, int col0, int g,
                                          const float* sInA, const float* sInB,
                                          ull accA[16], ull accB[12]) {
#pragma unroll
    for (int jm = 0; jm < 4; ++jm) {
        const float* wp  = Wt + (4 * NJ4 * g + jm) * Hd + col0;
        const float* spA = sInA + (NJ4 * g + jm * Q) * PITCH;
        const float* spB = sInB + (NJ4 * g + jm * Q) * PITCH;
#pragma unroll
        for (int jd = 0; jd < NJ4; ++jd) {
            float4 w4 = *reinterpret_cast<const float4*>(wp);
            ull vA[4], vB[3];
            ldrowP<4>(spA, vA);
            ldrowP<3>(spB, vB);
            ull w0 = pack2(w4.x, w4.x), w1 = pack2(w4.y, w4.y);
            ull w2 = pack2(w4.z, w4.z), w3 = pack2(w4.w, w4.w);
#pragma unroll
            for (int t = 0; t < 4; ++t) {
                accA[t]      = fma2(w0, vA[t], accA[t]);
                accA[4 + t]  = fma2(w1, vA[t], accA[4 + t]);
                accA[8 + t]  = fma2(w2, vA[t], accA[8 + t]);
                accA[12 + t] = fma2(w3, vA[t], accA[12 + t]);
            }
#pragma unroll
            for (int t = 0; t < 3; ++t) {
                accB[t]     = fma2(w0, vB[t], accB[t]);
                accB[3 + t] = fma2(w1, vB[t], accB[3 + t]);
                accB[6 + t] = fma2(w2, vB[t], accB[6 + t]);
                accB[9 + t] = fma2(w3, vB[t], accB[9 + t]);
            }
            wp += 4 * Hd;
            spA += PITCH;
            spB += PITCH;
        }
    }
}

// export: col c partials at slot offset c*4 (4-u64 stride regardless of PAIRS)
template<int PAIRS>
__device__ __forceinline__ void exportP(ull* p, const ull acc[4 * PAIRS]) {
#pragma unroll
    for (int c = 0; c < 4; ++c) {
        ull* b = p + c * 4;
        reinterpret_cast<ulonglong2*>(b)[0] =
            make_ulonglong2(acc[c * PAIRS + 0], acc[c * PAIRS + 1]);
        if (PAIRS == 3) {
            b[2] = acc[c * PAIRS + 2];
        } else {
            reinterpret_cast<ulonglong2*>(b)[1] =
                make_ulonglong2(acc[c * PAIRS + 2], acc[c * PAIRS + 3]);
        }
    }
}

// merge this thread's col (offset g*4 in each exporter slot) across 4 groups
template<int PAIRS>
__device__ __forceinline__ void mergeP(const ull* sRed, int quad, int g, ull m[4]) {
    m[0] = m[1] = m[2] = m[3] = 0ull;
#pragma unroll
    for (int gp = 0; gp < 4; ++gp) {
        const ull* p = sRed + (gp * 64 + quad) * SLOT + g * 4;
        ulonglong2 a = reinterpret_cast<const ulonglong2*>(p)[0];
        m[0] = add2(m[0], a.x); m[1] = add2(m[1], a.y);
        if (PAIRS == 3) {
            m[2] = add2(m[2], p[2]);
        } else {
            ulonglong2 b = reinterpret_cast<const ulonglong2*>(p)[1];
            m[2] = add2(m[2], b.x); m[3] = add2(m[3], b.y);
        }
    }
}

template<int PAIRS>
__device__ __forceinline__ void st_slice(float* rowbase, const ull m[4]) {
    ull* p = reinterpret_cast<ull*>(rowbase);
    reinterpret_cast<ulonglong2*>(p)[0] = make_ulonglong2(m[0], m[1]);
    if (PAIRS == 3) {
        p[2] = m[2];
    } else {
        reinterpret_cast<ulonglong2*>(p)[1] = make_ulonglong2(m[2], m[3]);
    }
}

// ---------------- merged transpose ----------------
__global__ void transpose_all(const float* __restrict__ wh,
                              const float* __restrict__ wout,
                              const float* __restrict__ wx) {
    __shared__ float tile[32][33];
    int b = blockIdx.x;
    const float* in; float* out; int rows, cols, bx;
    if (b < 64)       { in = wh;   out = g_whT;   rows = Hd; cols = Hd;  bx = b; }
    else if (b < 128) { in = wout; out = g_woutT; rows = Hd; cols = Hd;  bx = b - 64; }
    else              { in = wx;   out = g_wxT;   rows = Hd; cols = INd; bx = b - 128; }
    int nbx = cols / 32;
    int c0 = (bx % nbx) * 32, r0 = (bx / nbx) * 32;
    for (int dy = threadIdx.y; dy < 32; dy += 8)
        tile[dy][threadIdx.x] = in[(r0 + dy) * cols + (c0 + threadIdx.x)];
    __syncthreads();
    for (int dy = threadIdx.y; dy < 32; dy += 8)
        out[(c0 + dy) * rows + (r0 + threadIdx.x)] = tile[threadIdx.x][dy];
}

// ---------------- fused vector-field kernel: dual row-block, 1 CTA/SM ----------------
__global__ void __launch_bounds__(NTHR, 1)
fused_kernel(const float* __restrict__ hin, const float* __restrict__ xin,
             const float* __restrict__ xdin, const float* __restrict__ b0,
             const float* __restrict__ b1, float* __restrict__ out) {
    extern __shared__ __align__(16) char smraw[];
    ull*   sRedA = reinterpret_cast<ull*>(smraw);                  // [256][SLOT]
    ull*   sRedB = sRedA + NTHR * SLOT;                            // [256][SLOT]
    float* sA_A  = reinterpret_cast<float*>(sRedB + NTHR * SLOT);  // [256][PITCH]
    float* sB_A  = sA_A + Hd * PITCH;
    float* sA_B  = sB_A + Hd * PITCH;
    float* sB_B  = sA_B + Hd * PITCH;
    float* sXxA  = sB_B + Hd * PITCH;                              // [64][PITCH] x4
    float* sXdA  = sXxA + INd * PITCH;
    float* sXxB  = sXdA + INd * PITCH;
    float* sXdB  = sXxB + INd * PITCH;

    const int bid  = blockIdx.x;
    const int row0 = bid * ROWS;
    if (row0 >= Bsz) return;

    const int tid   = threadIdx.x;
    const int warp  = tid >> 5;
    const int lane  = tid & 31;
    const int g     = warp >> 1;                 // j-group 0..3 (warp-uniform)
    const int quad  = ((warp & 1) << 5) + lane;  // 0..63
    const int col0  = quad << 2;
    const int mycol = col0 + g;
    const int myrow = quad + (g << 6);           // phys(mycol)
    ull* slotA = sRedA + (g * 64 + quad) * SLOT;
    ull* slotB = sRedB + (g * 64 + quad) * SLOT;

    float bk0 = b0[mycol];
    float bk1 = b1[mycol];

    // ---- stage inputs (transposed + phys-permuted); clamp tail rows
    for (int e = tid; e < ROWS * Hd; e += NTHR) {
        int r = e >> 8, j = e & 255;
        int rr = row0 + r; if (rr > Bsz - 1) rr = Bsz - 1;
        int pr = (j >> 2) + ((j & 3) << 6);
        float vv = hin[rr * Hd + j];
        if (r < 8) sA_A[pr * PITCH + r] = vv;
        else       sA_B[pr * PITCH + (r - 8)] = vv;
    }
    for (int e = tid; e < ROWS * INd; e += NTHR) {
        int r = e >> 6, i = e & 63;
        int rr = row0 + r; if (rr > Bsz - 1) rr = Bsz - 1;
        int pr = (i >> 2) + ((i & 3) << 4);
        float vx = xin[rr * INd + i];
        float vd = xdin[rr * INd + i];
        if (r < 8) { sXxA[pr * PITCH + r] = vx;       sXdA[pr * PITCH + r] = vd; }
        else       { sXxB[pr * PITCH + r - 8] = vx;   sXdB[pr * PITCH + r - 8] = vd; }
    }
    __syncthreads();

    ull gateA[4], dthA[4], hdA[4];
    ull gateB[3], dthB[3], hdB[3];
    ull accA[16], accB[12];

    // ---- P1: l1 = x@wxT + h@whT + b0 -> gate, relu -> sB_*
#pragma unroll
    for (int q = 0; q < 16; ++q) accA[q] = 0ull;
#pragma unroll
    for (int q = 0; q < 12; ++q) accB[q] = 0ull;
    gemm_dual<4, 16>(g_wxT, col0, g, sXxA, sXxB, accA, accB);
    gemm_dual<16, 64>(g_whT, col0, g, sA_A, sA_B, accA, accB);
    exportP<4>(slotA, accA);
    exportP<3>(slotB, accB);
    __syncthreads();
    {
        ull bp = pack2(bk0, bk0);
        ull m[4], relu[4];
        mergeP<4>(sRedA, quad, g, m);
#pragma unroll
        for (int t = 0; t < 4; ++t) {
            m[t] = add2(m[t], bp);
            float a, b; unpack2(m[t], a, b);
            float ga = (a > 0.f) ? 1.f : 0.f;
            float gb = (b > 0.f) ? 1.f : 0.f;
            gateA[t] = pack2(ga, gb);
            relu[t] = pack2(ga * a, gb * b);
        }
        st_slice<4>(sB_A + myrow * PITCH, relu);
        mergeP<3>(sRedB, quad, g, m);
#pragma unroll
        for (int t = 0; t < 3; ++t) {
            m[t] = add2(m[t], bp);
            float a, b; unpack2(m[t], a, b);
            float ga = (a > 0.f) ? 1.f : 0.f;
            float gb = (b > 0.f) ? 1.f : 0.f;
            gateB[t] = pack2(ga, gb);
            relu[t] = pack2(ga * a, gb * b);
        }
        st_slice<3>(sB_B + myrow * PITCH, relu);
    }
    __syncthreads();

    // ---- P2: uu = xdot@wxT ; gated-u -> sA_*
#pragma unroll
    for (int q = 0; q < 16; ++q) accA[q] = 0ull;
#pragma unroll
    for (int q = 0; q < 12; ++q) accB[q] = 0ull;
    gemm_dual<4, 16>(g_wxT, col0, g, sXdA, sXdB, accA, accB);
    exportP<4>(slotA, accA);
    exportP<3>(slotB, accB);
    __syncthreads();
    {
        ull m[4];
        mergeP<4>(sRedA, quad, g, m);
#pragma unroll
        for (int t = 0; t < 4; ++t) m[t] = mul2(m[t], gateA[t]);
        st_slice<4>(sA_A + myrow * PITCH, m);
        mergeP<3>(sRedB, quad, g, m);
#pragma unroll
        for (int t = 0; t < 3; ++t) m[t] = mul2(m[t], gateB[t]);
        st_slice<3>(sA_B + myrow * PITCH, m);
    }
    __syncthreads();

    // ---- P3: lout = relu@woutT + b1 -> dth
#pragma unroll
    for (int q = 0; q < 16; ++q) accA[q] = 0ull;
#pragma unroll
    for (int q = 0; q < 12; ++q) accB[q] = 0ull;
    gemm_dual<16, 64>(g_woutT, col0, g, sB_A, sB_B, accA, accB);
    exportP<4>(slotA, accA);
    exportP<3>(slotB, accB);
    __syncthreads();
    {
        ull bp = pack2(bk1, bk1);
        ull m[4];
        mergeP<4>(sRedA, quad, g, m);
#pragma unroll
        for (int t = 0; t < 4; ++t) {
            ull L = add2(m[t], bp);
            float a, b; unpack2(L, a, b);
            float ta = tanhf(a), tb = tanhf(b);
            dthA[t] = pack2(1.f - ta * ta, 1.f - tb * tb);
        }
        mergeP<3>(sRedB, quad, g, m);
#pragma unroll
        for (int t = 0; t < 3; ++t) {
            ull L = add2(m[t], bp);
            float a, b; unpack2(L, a, b);
            float ta = tanhf(a), tb = tanhf(b);
            dthB[t] = pack2(1.f - ta * ta, 1.f - tb * tb);
        }
    }
    __syncthreads();

    // ---- P4: jx = gated-u@woutT ; curr = dth*jx -> sA_* ; hd = curr
#pragma unroll
    for (int q = 0; q < 16; ++q) accA[q] = 0ull;
#pragma unroll
    for (int q = 0; q < 12; ++q) accB[q] = 0ull;
    gemm_dual<16, 64>(g_woutT, col0, g, sA_A, sA_B, accA, accB);
    exportP<4>(slotA, accA);
    exportP<3>(slotB, accB);
    __syncthreads();
    {
        ull m[4];
        mergeP<4>(sRedA, quad, g, m);
#pragma unroll
        for (int t = 0; t < 4; ++t) { m[t] = mul2(m[t], dthA[t]); hdA[t] = m[t]; }
        st_slice<4>(sA_A + myrow * PITCH, m);
        mergeP<3>(sRedB, quad, g, m);
#pragma unroll
        for (int t = 0; t < 3; ++t) { m[t] = mul2(m[t], dthB[t]); hdB[t] = m[t]; }
        st_slice<3>(sA_B + myrow * PITCH, m);
    }
    __syncthreads();

    // ---- 8 Jh-power iterations: curr = dth * ((gate * (curr@whT)) @ woutT)
    for (int it = 0; it < KTERMS; ++it) {
#pragma unroll
        for (int q = 0; q < 16; ++q) accA[q] = 0ull;
#pragma unroll
        for (int q = 0; q < 12; ++q) accB[q] = 0ull;
        gemm_dual<16, 64>(g_whT, col0, g, sA_A, sA_B, accA, accB);
        exportP<4>(slotA, accA);
        exportP<3>(slotB, accB);
        __syncthreads();
        {
            ull m[4];
            mergeP<4>(sRedA, quad, g, m);
#pragma unroll
            for (int t = 0; t < 4; ++t) m[t] = mul2(m[t], gateA[t]);
            st_slice<4>(sB_A + myrow * PITCH, m);
            mergeP<3>(sRedB, quad, g, m);
#pragma unroll
            for (int t = 0; t < 3; ++t) m[t] = mul2(m[t], gateB[t]);
            st_slice<3>(sB_B + myrow * PITCH, m);
        }
        __syncthreads();
#pragma unroll
        for (int q = 0; q < 16; ++q) accA[q] = 0ull;
#pragma unroll
        for (int q = 0; q < 12; ++q) accB[q] = 0ull;
        gemm_dual<16, 64>(g_woutT, col0, g, sB_A, sB_B, accA, accB);
        exportP<4>(slotA, accA);
        exportP<3>(slotB, accB);
        __syncthreads();
        {
            ull m[4];
            mergeP<4>(sRedA, quad, g, m);
#pragma unroll
            for (int t = 0; t < 4; ++t) { m[t] = mul2(m[t], dthA[t]); hdA[t] = add2(hdA[t], m[t]); }
            st_slice<4>(sA_A + myrow * PITCH, m);
            mergeP<3>(sRedB, quad, g, m);
#pragma unroll
            for (int t = 0; t < 3; ++t) { m[t] = mul2(m[t], dthB[t]); hdB[t] = add2(hdB[t], m[t]); }
            st_slice<3>(sA_B + myrow * PITCH, m);
        }
        __syncthreads();
    }

    // ---- write h_dot: A rows row0..row0+7, B rows row0+8..row0+13 (guard tail)
#pragma unroll
    for (int t = 0; t < 4; ++t) {
        float a, b; unpack2(hdA[t], a, b);
        int r = row0 + 2 * t;
        if (r < Bsz)     out[r       * Hd + mycol] = a;
        if (r + 1 < Bsz) out[(r + 1) * Hd + mycol] = b;
    }
#pragma unroll
    for (int t = 0; t < 3; ++t) {
        float a, b; unpack2(hdB[t], a, b);
        int r = row0 + 8 + 2 * t;
        if (r < Bsz)     out[r       * Hd + mycol] = a;
        if (r + 1 < Bsz) out[(r + 1) * Hd + mycol] = b;
    }
}

#define SMEM_BYTES (2 * NTHR * SLOT * 8 + (4 * Hd + 4 * INd) * PITCH * 4)

extern "C" void kernel_launch(void* const* d_in, const int* in_sizes, int n_in,
                              void* d_out, int out_size) {
    (void)in_sizes; (void)n_in; (void)out_size;
    const float* h_   = (const float*)d_in[0];
    const float* x    = (const float*)d_in[1];
    const float* xdot = (const float*)d_in[2];
    const float* wx   = (const float*)d_in[3];
    const float* wh   = (const float*)d_in[4];
    const float* wout = (const float*)d_in[5];
    const float* b0   = (const float*)d_in[6];
    const float* b1   = (const float*)d_in[7];
    float* out = (float*)d_out;

    cudaFuncSetAttribute(fused_kernel, cudaFuncAttributeMaxDynamicSharedMemorySize, SMEM_BYTES);
    transpose_all<<<144, dim3(32, 8)>>>(wh, wout, wx);
    fused_kernel<<<NCTAS, NTHR, SMEM_BYTES>>>(h_, x, xdot, b0, b1, out);
}